// round 17
// baseline (speedup 1.0000x reference)
#include <cuda_runtime.h>
#include <cstdint>

#define T_STEPS 256
#define BATCH   128
#define KDIM    1536
#define F4      384     // KDIM/4 (float4 units)
#define NTHR    256     // warps 0-3: h-side, warps 4-7: c-side + x
#define STAGE_B 6144u   // F4 * 16 bytes

// HW tanh: single MUFU op, max rel err ~2^-11.
__device__ __forceinline__ float tanha(float x) {
    float y;
    asm("tanh.approx.f32 %0, %1;" : "=f"(y) : "f"(x));
    return y;
}

__device__ __forceinline__ void cp_async16(uint32_t dst, const void* src) {
    asm volatile("cp.async.cg.shared.global [%0], [%1], 16;" :: "r"(dst), "l"(src));
}
#define CP_COMMIT() asm volatile("cp.async.commit_group;" ::: "memory")
#define CP_WAIT2()  asm volatile("cp.async.wait_group 2;" ::: "memory")

// packed f32x2 fma
__device__ __forceinline__ void ffma2(unsigned long long& acc,
                                      unsigned long long a,
                                      unsigned long long b) {
    asm("fma.rn.f32x2 %0, %1, %2, %0;" : "+l"(acc) : "l"(a), "l"(b));
}
__device__ __forceinline__ float2 unpack2(unsigned long long v) {
    float2 f;
    asm("mov.b64 {%0, %1}, %2;" : "=f"(f.x), "=f"(f.y) : "l"(v));
    return f;
}

// 12-term dot product (3 float4 each side), 2 accumulator chains.
__device__ __forceinline__ float dot12(const float4* v, const float4* w) {
    float a0 = 0.0f, a1 = 0.0f;
    #pragma unroll
    for (int j = 0; j < 3; j++) {
        a0 = fmaf(v[j].x, w[j].x, fmaf(v[j].y, w[j].y, a0));
        a1 = fmaf(v[j].z, w[j].z, fmaf(v[j].w, w[j].w, a1));
    }
    return a0 + a1;
}

// ---------------------------------------------------------------------------
// One CTA per batch, 256 threads. Symmetric warp specialization:
//   warps 0-3 (h-side): own h + Wr. Per step: Hc/Hh dots -> 2-sum butterfly
//     (5 SHFL) -> STS rows 0,1 -> barrier -> tail (Hh,Ch,X5 rows) ->
//     ghb/gha (2 tanh) -> 12 h-tanh update + STG h.
//   warps 4-7 (c-side): own c + Wc + Wi + the 4-stage cp.async ring. Per
//     step: LDS x_{t+1}, refill, FFMA2 x-dots + Cc/Ch dots -> 4-sum
//     butterfly (6 SHFL) -> STS rows 2-5 -> barrier -> tail (Hc,Cc,X4) ->
//     gcb/gca (2 tanh) -> 12 c-tanh update (no STG).
// MUFU drain is split 14/14 warp-ops per SMSP pair instead of 28/0, so the
// two warps' post-barrier chains overlap on the MUFU pipe.
// ---------------------------------------------------------------------------
__global__ void __launch_bounds__(NTHR) fused_kernel(
    const float* __restrict__ inputs,
    const float* __restrict__ h0,
    const float* __restrict__ c0,
    const float* __restrict__ Wr,
    const float* __restrict__ br,
    const float* __restrict__ Wc,
    const float* __restrict__ bc,
    const float* __restrict__ Wi,
    const float* __restrict__ bi,
    float* __restrict__ out)
{
    __shared__ float      sG[2][6][4];   // [buf][row][warp]: Hc,Hh,Cc,Ch,X4,X5
    __shared__ ulonglong2 sX[4 * F4];    // 4 x 6KB input stages (packed)

    const int tid  = threadIdx.x;
    const int b    = blockIdx.x;
    const int warp = tid >> 5;
    const int lane = tid & 31;
    const int htid = tid & 127;          // dim index within role
    const bool isC = warp < 4;           // "compute"/h-side
    const int  hw  = warp & 3;

    const float4* in4 = (const float4*)inputs;
    float4* out4 = (float4*)out;

    // role-specific persistent registers
    float4 h[3], wr0[3], wr1[3];                       // h-side
    float4 cst[3], wc0[3], wc1[3];                     // c-side
    ulonglong2 wi0p[3], wi1p[3];                       // c-side
    if (isC) {
        const float4* Wr4 = (const float4*)Wr;
        #pragma unroll
        for (int j = 0; j < 3; j++) {
            const int p = htid + 128 * j;
            h[j]   = ((const float4*)h0)[b * F4 + p];
            wr0[j] = Wr4[p];
            wr1[j] = Wr4[F4 + p];
        }
    } else {
        const float4*     Wc4 = (const float4*)Wc;
        const ulonglong2* Wi2 = (const ulonglong2*)Wi;
        #pragma unroll
        for (int j = 0; j < 3; j++) {
            const int p = htid + 128 * j;
            cst[j]  = ((const float4*)c0)[b * F4 + p];
            wc0[j]  = Wc4[p];
            wc1[j]  = Wc4[F4 + p];
            wi0p[j] = Wi2[p];
            wi1p[j] = Wi2[F4 + p];
        }
    }
    const float hbr0 = 0.5f * br[0], hbr1 = 0.5f * br[1];
    const float hbc0 = 0.5f * bc[0], hbc1 = 0.5f * bc[1];
    const float bi0 = bi[0], bi1 = bi[1];

    const bool lo = lane < 16;
    const bool b3 = (lane & 8) != 0;

    const uint32_t sx_tid =
        (uint32_t)__cvta_generic_to_shared(&sX[0]) + (uint32_t)htid * 16u;
    const ulonglong2* sXu = &sX[0];

    // ---- prologue (c-side): proj(x_0) -> sG[1][4,5]; fill stages 1..3 ----
    if (!isC) {
        float4 x0[3], wi0f[3], wi1f[3];
        #pragma unroll
        for (int j = 0; j < 3; j++) {
            x0[j]   = in4[(long)b * F4 + htid + 128 * j];
            wi0f[j] = *(const float4*)&wi0p[j];
            wi1f[j] = *(const float4*)&wi1p[j];
        }
        float v4 = dot12(x0, wi0f);
        float v5 = dot12(x0, wi1f);

        #pragma unroll
        for (int s = 1; s <= 3; s++) {
            const float4* src = in4 + (long)s * BATCH * F4 + (long)b * F4 + htid;
            const uint32_t dst = sx_tid + (uint32_t)s * STAGE_B;
            cp_async16(dst,         src);
            cp_async16(dst + 2048u, src + 128);
            cp_async16(dst + 4096u, src + 256);
            CP_COMMIT();
        }

        float k  = lo ? v4 : v5;
        float s_ = lo ? v5 : v4;
        k += __shfl_xor_sync(~0u, s_, 16);
        k += __shfl_xor_sync(~0u, k, 8);
        k += __shfl_xor_sync(~0u, k, 4);
        k += __shfl_xor_sync(~0u, k, 2);
        k += __shfl_xor_sync(~0u, k, 1);
        if (lane == 0)  sG[1][4][hw] = k;
        if (lane == 16) sG[1][5][hw] = k;
    }
    __syncthreads();
    float Xc = 0.0f, Xh = 0.0f;
    if (isC) {
        float4 q = *(const float4*)sG[1][5];
        Xh = (q.x + q.y) + (q.z + q.w) + bi1;
    } else {
        float4 q = *(const float4*)sG[1][4];
        Xc = (q.x + q.y) + (q.z + q.w) + bi0;
    }

    // strength-reduced pointers
    const float4* srcp = in4 + (long)4 * BATCH * F4 + (long)b * F4 + htid; // x_{t+4}
    float4*       outp = out4 + (long)b * F4 + htid;

#define DO_STEP(SC, SW, BUF, SRC)                                              \
    {                                                                          \
        if (isC) {                                                             \
            /* h-side: Hc/Hh dots + 2-sum butterfly (5 SHFL) */                \
            float g0 = dot12(h, wr0), g1 = dot12(h, wr1);                      \
            float k  = lo ? g0 : g1;                                           \
            float s_ = lo ? g1 : g0;                                           \
            k += __shfl_xor_sync(~0u, s_, 16);                                 \
            k += __shfl_xor_sync(~0u, k, 8);                                   \
            k += __shfl_xor_sync(~0u, k, 4);                                   \
            k += __shfl_xor_sync(~0u, k, 2);                                   \
            k += __shfl_xor_sync(~0u, k, 1);                                   \
            if (lane == 0)  sG[BUF][0][hw] = k;                                \
            if (lane == 16) sG[BUF][1][hw] = k;                                \
        } else {                                                               \
            /* c-side: x_{t+1} proj + Cc/Ch dots + 4-sum butterfly */          \
            CP_WAIT2();                                                        \
            const ulonglong2* xs = sXu + (SC) * F4 + htid;                     \
            ulonglong2 x0 = xs[0], x1 = xs[128], x2 = xs[256];                 \
            {                                                                  \
                const uint32_t dst = sx_tid + (uint32_t)(SW) * STAGE_B;        \
                cp_async16(dst,         (SRC));                                \
                cp_async16(dst + 2048u, (SRC) + 128);                          \
                cp_async16(dst + 4096u, (SRC) + 256);                          \
                CP_COMMIT();                                                   \
            }                                                                  \
            unsigned long long a0 = 0ull, a1 = 0ull, q0 = 0ull, q1 = 0ull;     \
            ffma2(a0, x0.x, wi0p[0].x); ffma2(a1, x0.y, wi0p[0].y);            \
            ffma2(q0, x0.x, wi1p[0].x); ffma2(q1, x0.y, wi1p[0].y);            \
            ffma2(a0, x1.x, wi0p[1].x); ffma2(a1, x1.y, wi0p[1].y);            \
            ffma2(q0, x1.x, wi1p[1].x); ffma2(q1, x1.y, wi1p[1].y);            \
            ffma2(a0, x2.x, wi0p[2].x); ffma2(a1, x2.y, wi0p[2].y);            \
            ffma2(q0, x2.x, wi1p[2].x); ffma2(q1, x2.y, wi1p[2].y);            \
            float2 pa0 = unpack2(a0), pa1 = unpack2(a1);                       \
            float2 pb0 = unpack2(q0), pb1 = unpack2(q1);                       \
            float x4 = (pa0.x + pa0.y) + (pa1.x + pa1.y);                      \
            float x5 = (pb0.x + pb0.y) + (pb1.x + pb1.y);                      \
            float cc = dot12(cst, wc0), ch = dot12(cst, wc1);                  \
            /* 4-sum butterfly (Cc, Ch, X4, X5): 6 SHFL */                     \
            float rA = __shfl_xor_sync(~0u, lo ? x4 : cc, 16);                 \
            float rB = __shfl_xor_sync(~0u, lo ? x5 : ch, 16);                 \
            if (lo) { cc += rA; ch += rB; } else { x4 += rA; x5 += rB; }       \
            float P  = lo ? (b3 ? ch : cc) : (b3 ? x5 : x4);                   \
            float sP = lo ? (b3 ? cc : ch) : (b3 ? x4 : x5);                   \
            P += __shfl_xor_sync(~0u, sP, 8);                                  \
            P += __shfl_xor_sync(~0u, P, 4);                                   \
            P += __shfl_xor_sync(~0u, P, 2);                                   \
            P += __shfl_xor_sync(~0u, P, 1);                                   \
            /* lane0=Cc,8=Ch,16=X4,24=X5 -> rows 2..5 */                       \
            if ((lane & 7) == 0) sG[BUF][2 + (lane >> 3)][hw] = P;             \
        }                                                                      \
        __syncthreads();                                                       \
        if (isC) {                                                             \
            float4 qh = *(const float4*)sG[BUF][1];   /* Hh */                 \
            float4 qc = *(const float4*)sG[BUF][3];   /* Ch */                 \
            float4 qx = *(const float4*)sG[BUF][5];   /* X5 */                 \
            float sHh = (qh.x + qh.y) + (qh.z + qh.w);                         \
            float sCh = (qc.x + qc.y) + (qc.z + qc.w);                         \
            float ghb = fmaf(-0.5f, tanha(fmaf(0.5f, sHh, hbr1)), 0.5f);       \
            float sgC = fmaf(-0.5f, tanha(fmaf(0.5f, sCh, hbc1)), 0.5f);       \
            float gha = sgC * Xh;                                              \
            Xh = (qx.x + qx.y) + (qx.z + qx.w) + bi1;                          \
            _Pragma("unroll")                                                  \
            for (int j = 0; j < 3; j++) {                                      \
                h[j].x = tanha(fmaf(ghb, h[j].x, gha));                        \
                h[j].y = tanha(fmaf(ghb, h[j].y, gha));                        \
                h[j].z = tanha(fmaf(ghb, h[j].z, gha));                        \
                h[j].w = tanha(fmaf(ghb, h[j].w, gha));                        \
                outp[128 * j] = h[j];                                          \
            }                                                                  \
        } else {                                                               \
            float4 qh = *(const float4*)sG[BUF][0];   /* Hc */                 \
            float4 qc = *(const float4*)sG[BUF][2];   /* Cc */                 \
            float4 qx = *(const float4*)sG[BUF][4];   /* X4 */                 \
            float sHc = (qh.x + qh.y) + (qh.z + qh.w);                         \
            float sCc = (qc.x + qc.y) + (qc.z + qc.w);                         \
            float gcb = fmaf(-0.5f, tanha(fmaf(0.5f, sCc, hbc0)), 0.5f);       \
            float sgH = fmaf(-0.5f, tanha(fmaf(0.5f, sHc, hbr0)), 0.5f);       \
            float gca = sgH * Xc;                                              \
            Xc = (qx.x + qx.y) + (qx.z + qx.w) + bi0;                          \
            _Pragma("unroll")                                                  \
            for (int j = 0; j < 3; j++) {                                      \
                cst[j].x = tanha(fmaf(gcb, cst[j].x, gca));                    \
                cst[j].y = tanha(fmaf(gcb, cst[j].y, gca));                    \
                cst[j].z = tanha(fmaf(gcb, cst[j].z, gca));                    \
                cst[j].w = tanha(fmaf(gcb, cst[j].w, gca));                    \
            }                                                                  \
        }                                                                      \
        outp += BATCH * F4;                                                    \
    }

    // main loop: 252 steps, unrolled by 4 (static stage / parity)
    for (int tb = 0; tb < 252; tb += 4) {
        DO_STEP(1, 0, 0, srcp); srcp += BATCH * F4;
        DO_STEP(2, 1, 1, srcp); srcp += BATCH * F4;
        DO_STEP(3, 2, 0, srcp); srcp += BATCH * F4;
        DO_STEP(0, 3, 1, srcp); srcp += BATCH * F4;
    }
    // tail: steps 252..255, refill source clamped to x_255
    {
        const float4* srcL = in4 + (long)(T_STEPS - 1) * BATCH * F4
                           + (long)b * F4 + htid;
        DO_STEP(1, 0, 0, srcL);
        DO_STEP(2, 1, 1, srcL);
        DO_STEP(3, 2, 0, srcL);
        DO_STEP(0, 3, 1, srcL);
    }
#undef DO_STEP

    // final hT (h-side), cT (c-side)
    const long offH = (long)T_STEPS * BATCH * F4;
    const long offC = offH + (long)BATCH * F4;
    if (isC) {
        #pragma unroll
        for (int j = 0; j < 3; j++)
            out4[offH + (long)b * F4 + htid + 128 * j] = h[j];
    } else {
        #pragma unroll
        for (int j = 0; j < 3; j++)
            out4[offC + (long)b * F4 + htid + 128 * j] = cst[j];
    }
}

extern "C" void kernel_launch(void* const* d_in, const int* in_sizes, int n_in,
                              void* d_out, int out_size)
{
    const float* inputs = (const float*)d_in[0];
    const float* h0     = (const float*)d_in[1];
    const float* c0     = (const float*)d_in[2];
    const float* Wr     = (const float*)d_in[3];
    const float* br     = (const float*)d_in[4];
    const float* Wc     = (const float*)d_in[5];
    const float* bc     = (const float*)d_in[6];
    const float* Wi     = (const float*)d_in[7];
    const float* bi     = (const float*)d_in[8];
    float* out = (float*)d_out;

    fused_kernel<<<BATCH, NTHR>>>(inputs, h0, c0, Wr, br, Wc, bc, Wi, bi, out);
}